// round 12
// baseline (speedup 1.0000x reference)
#include <cuda_runtime.h>
#include <cuda_fp16.h>
#include <math.h>
#include <stdint.h>

#define Bb   8
#define Cc   256
#define Hh   64
#define Ww   64
#define Oo   256
#define HW   4096
#define OCOFF 27
#define KTOT 2304            /* K = C*9 */
#define NTOT 32768           /* B*H*W */
#define CSPLIT 8
#define CPG (Cc / CSPLIT)

// ---------------- scratch (__device__ globals) ------------------------------
__device__ float    g_part[CSPLIT][Bb * OCOFF * HW];   // offset-conv partials
__device__ uint16_t g_cols[(size_t)KTOT * NTOT];       // fp16 cols, [k][n]
__device__ uint16_t g_A[Oo * KTOT];                    // weight fp16, [o][k]
__device__ __half   g_xT[(size_t)Bb * HW * Cc];        // fp16 x, channel-last

// ---------------- helpers ----------------------------------------------------
__device__ __forceinline__ uint32_t smem_u32(const void* p) {
    uint32_t a;
    asm("{ .reg .u64 t; cvta.to.shared.u64 t, %1; cvt.u32.u64 %0, t; }" : "=r"(a) : "l"(p));
    return a;
}
__device__ __forceinline__ uint32_t swz(uint32_t off)  { return off ^ ((off >> 3) & 0x70); }
__device__ __forceinline__ uint32_t swz2(uint32_t off) { return off ^ ((off >> 4) & 0x70); }

__device__ __forceinline__ void cp16(uint32_t dst, const void* src) {
    asm volatile("cp.async.cg.shared.global [%0], [%1], 16;" :: "r"(dst), "l"(src));
}
#define CP_COMMIT() asm volatile("cp.async.commit_group;" ::: "memory")
#define CP_WAIT2()  asm volatile("cp.async.wait_group 2;" ::: "memory")

__device__ __forceinline__ void ldsm4(uint32_t* r, uint32_t addr) {
    asm volatile("ldmatrix.sync.aligned.m8n8.x4.shared.b16 {%0,%1,%2,%3}, [%4];"
                 : "=r"(r[0]), "=r"(r[1]), "=r"(r[2]), "=r"(r[3]) : "r"(addr));
}
__device__ __forceinline__ void ldsm4t(uint32_t* r, uint32_t addr) {
    asm volatile("ldmatrix.sync.aligned.m8n8.x4.trans.shared.b16 {%0,%1,%2,%3}, [%4];"
                 : "=r"(r[0]), "=r"(r[1]), "=r"(r[2]), "=r"(r[3]) : "r"(addr));
}
__device__ __forceinline__ void mma16816(float* c, const uint32_t* a,
                                         uint32_t b0, uint32_t b1) {
    asm volatile("mma.sync.aligned.m16n8k16.row.col.f32.f16.f16.f32 "
                 "{%0,%1,%2,%3}, {%4,%5,%6,%7}, {%8,%9}, {%0,%1,%2,%3};"
                 : "+f"(c[0]), "+f"(c[1]), "+f"(c[2]), "+f"(c[3])
                 : "r"(a[0]), "r"(a[1]), "r"(a[2]), "r"(a[3]), "r"(b0), "r"(b1));
}
__device__ __forceinline__ void fma2(unsigned long long& a, unsigned long long x,
                                     unsigned long long w) {
    asm("fma.rn.f32x2 %0, %1, %2, %0;" : "+l"(a) : "l"(x), "l"(w));
}
__device__ __forceinline__ unsigned long long pack2(float v) {
    unsigned long long r;
    asm("mov.b64 %0, {%1, %1};" : "=l"(r) : "r"(__float_as_uint(v)));
    return r;
}
__device__ __forceinline__ void cvt8(const uint4& u, float* f) {
    const __half2* h = (const __half2*)&u;
#pragma unroll
    for (int i = 0; i < 4; ++i) {
        float2 t = __half22float2(h[i]);
        f[2 * i] = t.x; f[2 * i + 1] = t.y;
    }
}

// ===========================================================================
// Kernel X: x [b][c][hw] fp32 -> g_xT [b][hw][c] fp16  (smem tile transpose)
// block (32,8), tile 32x32; grid (HW/32, Cc/32, Bb)
// ===========================================================================
__global__ __launch_bounds__(256)
void xtrans_kernel(const float* __restrict__ x) {
    __shared__ __half tile[32][33];
    int b   = blockIdx.z;
    int hw0 = blockIdx.x * 32;
    int c0  = blockIdx.y * 32;
    int tx  = threadIdx.x;
    int ty  = threadIdx.y;

#pragma unroll
    for (int i = ty; i < 32; i += 8)
        tile[tx][i] = __float2half_rn(
            x[((size_t)b * Cc + c0 + i) * HW + hw0 + tx]);
    __syncthreads();
#pragma unroll
    for (int i = ty; i < 32; i += 8)
        g_xT[((size_t)b * HW + hw0 + i) * Cc + c0 + tx] = tile[i][tx];
}

// ===========================================================================
// Kernel A: offset conv partials (32-ch groups), packed f32x2 math.
// ===========================================================================
__global__ __launch_bounds__(256)
void offset_conv_part(const float* __restrict__ x,
                      const float* __restrict__ w_off) {
    __shared__ __align__(16) float swt[CPG * 252];
    __shared__ float sx[2][6][64];

    int cg = blockIdx.x & 7;
    int hs = (blockIdx.x >> 3) & 15;
    int b  = blockIdx.x >> 7;
    int h0 = hs << 2;
    int tid = threadIdx.x;
    int ty = tid >> 6;
    int w  = tid & 63;
    int h  = h0 + ty;
    int c0 = cg * CPG;

    const float* xb = x + (size_t)b * Cc * HW;

    for (int i = tid; i < 288; i += 256) swt[i * 28 + 27] = 0.f;
    for (int i = tid; i < OCOFF * 288; i += 256) {
        int oc  = i / 288;
        int rem = i - oc * 288;
        int ci  = rem / 9, t = rem - ci * 9;
        swt[ci * 252 + t * 28 + oc] = w_off[(size_t)oc * KTOT + c0 * 9 + rem];
    }

    bool ldr = tid < 96;
    int lrow = tid >> 4;
    int lseg = tid & 15;
    int yy   = h0 - 1 + lrow;
    bool yok = (yy >= 0) & (yy < Hh);

    if (ldr) {
        float4 v = make_float4(0.f, 0.f, 0.f, 0.f);
        if (yok) v = *(const float4*)&xb[(size_t)c0 * HW + yy * 64 + lseg * 4];
        *(float4*)&sx[0][lrow][lseg * 4] = v;
    }
    __syncthreads();

    unsigned long long acc2[14];
#pragma unroll
    for (int j = 0; j < 14; ++j) acc2[j] = 0ULL;

    for (int ci = 0; ci < CPG; ++ci) {
        float4 nv = make_float4(0.f, 0.f, 0.f, 0.f);
        if (ci + 1 < CPG && ldr && yok)
            nv = *(const float4*)&xb[(size_t)(c0 + ci + 1) * HW + yy * 64 + lseg * 4];

        const float (*cur)[64] = sx[ci & 1];
        float xv[9];
#pragma unroll
        for (int dy = 0; dy < 3; ++dy)
#pragma unroll
            for (int dx = 0; dx < 3; ++dx) {
                int xx = w - 1 + dx;
                xv[dy * 3 + dx] = (xx >= 0 && xx < Ww) ? cur[ty + dy][xx] : 0.f;
            }

#pragma unroll
        for (int t = 0; t < 9; ++t) {
            unsigned long long xp = pack2(xv[t]);
            const ulonglong2* wp = (const ulonglong2*)&swt[ci * 252 + t * 28];
#pragma unroll
            for (int j = 0; j < 7; ++j) {
                ulonglong2 w2 = wp[j];
                fma2(acc2[2 * j],     xp, w2.x);
                fma2(acc2[2 * j + 1], xp, w2.y);
            }
        }

        if (ci + 1 < CPG && ldr)
            *(float4*)&sx[(ci + 1) & 1][lrow][lseg * 4] = nv;
        __syncthreads();
    }

    size_t outb = ((size_t)b * OCOFF) * HW + h * 64 + w;
#pragma unroll
    for (int j = 0; j < 14; ++j) {
        float lo = __uint_as_float((uint32_t)acc2[j]);
        float hi = __uint_as_float((uint32_t)(acc2[j] >> 32));
        int oc0 = 2 * j, oc1 = 2 * j + 1;
        g_part[cg][outb + (size_t)oc0 * HW] = lo;
        if (oc1 < OCOFF) g_part[cg][outb + (size_t)oc1 * HW] = hi;
    }
}

// ===========================================================================
// Kernel W: weights -> fp16 plane
// ===========================================================================
__global__ void wprep_kernel(const float* __restrict__ weight) {
    int idx = blockIdx.x * 256 + threadIdx.x;
    if (idx >= Oo * KTOT) return;
    g_A[idx] = __half_as_ushort(__float2half_rn(weight[idx]));
}

// ===========================================================================
// Kernel B: fused offset-reduce + deform-sample -> fp16 cols [k][n].
// Channel-last gathers: 4 x LDG.128 per 8 channels (vs 32 scalar gathers).
// ===========================================================================
__global__ __launch_bounds__(288)
void build_cols_kernel(const float* __restrict__ b_off) {
    int tid = threadIdx.x;
    int n_l = tid & 31;
    int kk  = tid >> 5;                // 0..8
    int n0  = blockIdx.x * 32;
    int n   = n0 + n_l;
    int b   = n >> 12;
    int hw  = n & 4095;
    int h   = hw >> 6, w = hw & 63;

    size_t pbase = ((size_t)b * OCOFF) * HW + hw;
    float oy = b_off[kk], ox = b_off[9 + kk], ms = b_off[18 + kk];
#pragma unroll
    for (int g = 0; g < CSPLIT; ++g) {
        oy += g_part[g][pbase + (size_t)kk * HW];
        ox += g_part[g][pbase + (size_t)(9 + kk) * HW];
        ms += g_part[g][pbase + (size_t)(18 + kk) * HW];
    }
    float m = 1.f / (1.f + expf(-ms));

    float py = (float)(h - 1 + kk / 3) + oy;
    float px = (float)(w - 1 + kk % 3) + ox;
    float y0f = floorf(py), x0f = floorf(px);
    float wy = py - y0f, wx = px - x0f;
    int y0 = (int)y0f, x0 = (int)x0f;

    bool yv0 = (y0 >= 0) & (y0 < Hh);
    bool yv1 = (y0 + 1 >= 0) & (y0 + 1 < Hh);
    bool xv0 = (x0 >= 0) & (x0 < Ww);
    bool xv1 = (x0 + 1 >= 0) & (x0 + 1 < Ww);

    float w00 = m * (1.f - wy) * (1.f - wx) * (float)(yv0 & xv0);
    float w01 = m * (1.f - wy) * wx         * (float)(yv0 & xv1);
    float w10 = m * wy * (1.f - wx)         * (float)(yv1 & xv0);
    float w11 = m * wy * wx                 * (float)(yv1 & xv1);

    int y0c = min(max(y0, 0), Hh - 1);
    int y1c = min(max(y0 + 1, 0), Hh - 1);
    int x0c = min(max(x0, 0), Ww - 1);
    int x1c = min(max(x0 + 1, 0), Ww - 1);

    const __half* xt = g_xT + (size_t)b * HW * Cc;
    const uint4* p00 = (const uint4*)(xt + (size_t)(y0c * 64 + x0c) * Cc);
    const uint4* p01 = (const uint4*)(xt + (size_t)(y0c * 64 + x1c) * Cc);
    const uint4* p10 = (const uint4*)(xt + (size_t)(y1c * 64 + x0c) * Cc);
    const uint4* p11 = (const uint4*)(xt + (size_t)(y1c * 64 + x1c) * Cc);

#pragma unroll 1
    for (int c8 = 0; c8 < Cc / 8; ++c8) {
        uint4 u00 = p00[c8], u01 = p01[c8], u10 = p10[c8], u11 = p11[c8];
        float f00[8], f01[8], f10[8], f11[8];
        cvt8(u00, f00); cvt8(u01, f01); cvt8(u10, f10); cvt8(u11, f11);
#pragma unroll
        for (int cl = 0; cl < 8; ++cl) {
            float val = f00[cl] * w00 + f01[cl] * w01
                      + f10[cl] * w10 + f11[cl] * w11;
            size_t off = (size_t)((c8 * 8 + cl) * 9 + kk) * NTOT + n;
            g_cols[off] = __half_as_ushort(__float2half_rn(val));
        }
    }
}

// ===========================================================================
// Kernel C: single-chain fp16 HMMA GEMM.  M=256 x N=128, K=2304.
// 512 threads, 16 warps (4M x 4N, warp tile 64x32), 4-stage cp.async.
// ===========================================================================
#define B_OFF  32768
#define STAGEB 49152
#define GSM    196608
#define NCHUNK 36

__device__ __forceinline__ void load_chunk(uint32_t sbu, uint32_t stoff, int chunk,
                                           int bn, int tid) {
    int kw = chunk * 64;
    uint32_t base = sbu + stoff;
    int r = tid >> 3, q = tid & 7;
#pragma unroll
    for (int rr = 0; rr < 4; ++rr) {
        int row = r + rr * 64;
        uint32_t o = swz((uint32_t)(row * 128 + q * 16));
        cp16(base + o, &g_A[(size_t)row * KTOT + kw + q * 8]);
    }
    {
        const uint16_t* s = &g_cols[(size_t)(kw + r) * NTOT + bn];
        cp16(base + B_OFF + swz2((uint32_t)(r * 256 + q * 16)),       s + q * 8);
        cp16(base + B_OFF + swz2((uint32_t)(r * 256 + (q + 8) * 16)), s + (q + 8) * 8);
    }
}

__global__ __launch_bounds__(512, 1)
void gemm_mma_kernel(const float* __restrict__ bias,
                     const float* __restrict__ gamma,
                     const float* __restrict__ beta,
                     const float* __restrict__ rmean,
                     const float* __restrict__ rvar,
                     float* __restrict__ out) {
    extern __shared__ char smc[];
    uint32_t sbu = smem_u32(smc);
    int tid  = threadIdx.x;
    int lane = tid & 31;
    int wid  = tid >> 5;
    int bn = blockIdx.x * 128;
    int warp_m = wid & 3;
    int warp_n = wid >> 2;

    int mi   = lane >> 3;
    int mrow = lane & 7;
    int rbit = ((mi & 1) << 3) + mrow;
    int cbit = (mi >> 1) << 4;
    int klane = ((mi >> 1) << 3) + mrow;
    int nlane = (mi & 1) << 3;

    float acc[4][4][4];
#pragma unroll
    for (int a = 0; a < 4; ++a)
#pragma unroll
        for (int b2 = 0; b2 < 4; ++b2)
#pragma unroll
            for (int c2 = 0; c2 < 4; ++c2) acc[a][b2][c2] = 0.f;

    load_chunk(sbu, 0 * STAGEB, 0, bn, tid); CP_COMMIT();
    load_chunk(sbu, 1 * STAGEB, 1, bn, tid); CP_COMMIT();
    load_chunk(sbu, 2 * STAGEB, 2, bn, tid); CP_COMMIT();

    int arow0 = warp_m * 64;
    int brow0 = warp_n * 32;

    for (int i = 0; i < NCHUNK; ++i) {
        int st = i & 3;
        CP_WAIT2();
        __syncthreads();

        if (i + 3 < NCHUNK)
            load_chunk(sbu, ((i + 3) & 3) * STAGEB, i + 3, bn, tid);
        CP_COMMIT();

        uint32_t base = sbu + st * STAGEB;
#pragma unroll
        for (int ks = 0; ks < 4; ++ks) {
            uint32_t bq[2][4], af[4][4];
#pragma unroll
            for (int ng = 0; ng < 2; ++ng)
                ldsm4t(bq[ng], base + B_OFF +
                       swz2((uint32_t)((ks * 16 + klane) * 256
                            + (brow0 + ng * 16 + nlane) * 2)));
#pragma unroll
            for (int mt = 0; mt < 4; ++mt)
                ldsm4(af[mt], base +
                      swz((uint32_t)((arow0 + mt * 16 + rbit) * 128 + ks * 32 + cbit)));

#pragma unroll
            for (int mt = 0; mt < 4; ++mt)
#pragma unroll
                for (int ng = 0; ng < 2; ++ng) {
                    mma16816(acc[mt][ng * 2 + 0], af[mt], bq[ng][0], bq[ng][2]);
                    mma16816(acc[mt][ng * 2 + 1], af[mt], bq[ng][1], bq[ng][3]);
                }
        }
        __syncthreads();
    }

    int nbase = bn + warp_n * 32;
#pragma unroll
    for (int mt = 0; mt < 4; ++mt) {
        int o0 = warp_m * 64 + mt * 16 + (lane >> 2);
        int o1 = o0 + 8;
        float inv0 = gamma[o0] * rsqrtf(rvar[o0] + 1e-5f);
        float sh0  = beta[o0] - rmean[o0] * inv0 + bias[o0] * inv0;
        float inv1 = gamma[o1] * rsqrtf(rvar[o1] + 1e-5f);
        float sh1  = beta[o1] - rmean[o1] * inv1 + bias[o1] * inv1;
#pragma unroll
        for (int nt = 0; nt < 4; ++nt) {
            int n = nbase + nt * 8 + ((lane & 3) << 1);
            int bimg = n >> 12;
            int hw   = n & 4095;
            float2 v0, v1;
            v0.x = fmaxf(fmaf(acc[mt][nt][0], inv0, sh0), 0.f);
            v0.y = fmaxf(fmaf(acc[mt][nt][1], inv0, sh0), 0.f);
            v1.x = fmaxf(fmaf(acc[mt][nt][2], inv1, sh1), 0.f);
            v1.y = fmaxf(fmaf(acc[mt][nt][3], inv1, sh1), 0.f);
            *(float2*)&out[(((size_t)(bimg * Oo + o0)) << 12) + hw] = v0;
            *(float2*)&out[(((size_t)(bimg * Oo + o1)) << 12) + hw] = v1;
        }
    }
}

// ===========================================================================
extern "C" void kernel_launch(void* const* d_in, const int* in_sizes, int n_in,
                              void* d_out, int out_size) {
    const float* x      = (const float*)d_in[0];
    const float* w_off  = (const float*)d_in[1];
    const float* b_off  = (const float*)d_in[2];
    const float* weight = (const float*)d_in[3];
    const float* bias   = (const float*)d_in[4];
    const float* gamma  = (const float*)d_in[5];
    const float* beta   = (const float*)d_in[6];
    const float* rmean  = (const float*)d_in[7];
    const float* rvar   = (const float*)d_in[8];
    float* out = (float*)d_out;

    cudaFuncSetAttribute(gemm_mma_kernel,
                         cudaFuncAttributeMaxDynamicSharedMemorySize, GSM);

    wprep_kernel<<<(Oo * KTOT + 255) / 256, 256>>>(weight);
    {
        dim3 grid(HW / 32, Cc / 32, Bb);
        dim3 blk(32, 8);
        xtrans_kernel<<<grid, blk>>>(x);
    }
    offset_conv_part<<<Bb * 16 * CSPLIT, 256>>>(x, w_off);
    build_cols_kernel<<<NTOT / 32, 288>>>(b_off);

    gemm_mma_kernel<<<NTOT / 128, 512, GSM>>>(bias, gamma, beta, rmean, rvar, out);
}

// round 13
// speedup vs baseline: 1.0791x; 1.0791x over previous
#include <cuda_runtime.h>
#include <cuda_fp16.h>
#include <math.h>
#include <stdint.h>

#define Bb   8
#define Cc   256
#define Hh   64
#define Ww   64
#define Oo   256
#define HW   4096
#define OCOFF 27
#define KTOT 2304            /* K = C*9 */
#define NTOT 32768           /* B*H*W */
#define CSPLIT 8
#define CPG (Cc / CSPLIT)

// ---------------- scratch (__device__ globals) ------------------------------
__device__ float    g_part[CSPLIT][Bb * OCOFF * HW];   // offset-conv partials
__device__ uint16_t g_cols[(size_t)KTOT * NTOT];       // fp16 cols, [k][n]
__device__ uint16_t g_A[Oo * KTOT];                    // weight fp16, [o][k]
__device__ __half   g_x16[(size_t)Bb * Cc * HW];       // fp16 copy of x

// ---------------- helpers ----------------------------------------------------
__device__ __forceinline__ uint32_t smem_u32(const void* p) {
    uint32_t a;
    asm("{ .reg .u64 t; cvta.to.shared.u64 t, %1; cvt.u32.u64 %0, t; }" : "=r"(a) : "l"(p));
    return a;
}
__device__ __forceinline__ uint32_t swz(uint32_t off)  { return off ^ ((off >> 3) & 0x70); }
__device__ __forceinline__ uint32_t swz2(uint32_t off) { return off ^ ((off >> 4) & 0x70); }

__device__ __forceinline__ void cp16(uint32_t dst, const void* src) {
    asm volatile("cp.async.cg.shared.global [%0], [%1], 16;" :: "r"(dst), "l"(src));
}
#define CP_COMMIT() asm volatile("cp.async.commit_group;" ::: "memory")
#define CP_WAIT2()  asm volatile("cp.async.wait_group 2;" ::: "memory")

__device__ __forceinline__ void ldsm4(uint32_t* r, uint32_t addr) {
    asm volatile("ldmatrix.sync.aligned.m8n8.x4.shared.b16 {%0,%1,%2,%3}, [%4];"
                 : "=r"(r[0]), "=r"(r[1]), "=r"(r[2]), "=r"(r[3]) : "r"(addr));
}
__device__ __forceinline__ void ldsm4t(uint32_t* r, uint32_t addr) {
    asm volatile("ldmatrix.sync.aligned.m8n8.x4.trans.shared.b16 {%0,%1,%2,%3}, [%4];"
                 : "=r"(r[0]), "=r"(r[1]), "=r"(r[2]), "=r"(r[3]) : "r"(addr));
}
__device__ __forceinline__ void mma16816(float* c, const uint32_t* a,
                                         uint32_t b0, uint32_t b1) {
    asm volatile("mma.sync.aligned.m16n8k16.row.col.f32.f16.f16.f32 "
                 "{%0,%1,%2,%3}, {%4,%5,%6,%7}, {%8,%9}, {%0,%1,%2,%3};"
                 : "+f"(c[0]), "+f"(c[1]), "+f"(c[2]), "+f"(c[3])
                 : "r"(a[0]), "r"(a[1]), "r"(a[2]), "r"(a[3]), "r"(b0), "r"(b1));
}
__device__ __forceinline__ void fma2(unsigned long long& a, unsigned long long x,
                                     unsigned long long w) {
    asm("fma.rn.f32x2 %0, %1, %2, %0;" : "+l"(a) : "l"(x), "l"(w));
}
__device__ __forceinline__ unsigned long long pack2(float v) {
    unsigned long long r;
    asm("mov.b64 %0, {%1, %1};" : "=l"(r) : "r"(__float_as_uint(v)));
    return r;
}

// ===========================================================================
// Kernel P: fused prep — x -> fp16 copy (blocks [0, XB)), weights -> fp16
// (blocks [XB, XB+WB))
// ===========================================================================
#define XB 8192     /* 8.39M elems / 4 per thread / 256 threads */
#define WB 2304     /* 589824 / 256 */
__global__ void prep_kernel(const float* __restrict__ x,
                            const float* __restrict__ weight) {
    int blk = blockIdx.x;
    if (blk < XB) {
        size_t i = ((size_t)blk * 256 + threadIdx.x) * 4;
        float4 v = *(const float4*)&x[i];
        __half2 lo = __floats2half2_rn(v.x, v.y);
        __half2 hi = __floats2half2_rn(v.z, v.w);
        *(uint32_t*)&g_x16[i]     = *(uint32_t*)&lo;
        *(uint32_t*)&g_x16[i + 2] = *(uint32_t*)&hi;
    } else {
        int idx = (blk - XB) * 256 + threadIdx.x;
        g_A[idx] = __half_as_ushort(__float2half_rn(weight[idx]));
    }
}

// ===========================================================================
// Kernel A: offset conv partials (32-ch groups), packed f32x2 math.
// ===========================================================================
__global__ __launch_bounds__(256)
void offset_conv_part(const float* __restrict__ x,
                      const float* __restrict__ w_off) {
    __shared__ __align__(16) float swt[CPG * 252];
    __shared__ float sx[2][6][64];

    int cg = blockIdx.x & 7;
    int hs = (blockIdx.x >> 3) & 15;
    int b  = blockIdx.x >> 7;
    int h0 = hs << 2;
    int tid = threadIdx.x;
    int ty = tid >> 6;
    int w  = tid & 63;
    int h  = h0 + ty;
    int c0 = cg * CPG;

    const float* xb = x + (size_t)b * Cc * HW;

    for (int i = tid; i < 288; i += 256) swt[i * 28 + 27] = 0.f;
    for (int i = tid; i < OCOFF * 288; i += 256) {
        int oc  = i / 288;
        int rem = i - oc * 288;
        int ci  = rem / 9, t = rem - ci * 9;
        swt[ci * 252 + t * 28 + oc] = w_off[(size_t)oc * KTOT + c0 * 9 + rem];
    }

    bool ldr = tid < 96;
    int lrow = tid >> 4;
    int lseg = tid & 15;
    int yy   = h0 - 1 + lrow;
    bool yok = (yy >= 0) & (yy < Hh);

    if (ldr) {
        float4 v = make_float4(0.f, 0.f, 0.f, 0.f);
        if (yok) v = *(const float4*)&xb[(size_t)c0 * HW + yy * 64 + lseg * 4];
        *(float4*)&sx[0][lrow][lseg * 4] = v;
    }
    __syncthreads();

    unsigned long long acc2[14];
#pragma unroll
    for (int j = 0; j < 14; ++j) acc2[j] = 0ULL;

    for (int ci = 0; ci < CPG; ++ci) {
        float4 nv = make_float4(0.f, 0.f, 0.f, 0.f);
        if (ci + 1 < CPG && ldr && yok)
            nv = *(const float4*)&xb[(size_t)(c0 + ci + 1) * HW + yy * 64 + lseg * 4];

        const float (*cur)[64] = sx[ci & 1];
        float xv[9];
#pragma unroll
        for (int dy = 0; dy < 3; ++dy)
#pragma unroll
            for (int dx = 0; dx < 3; ++dx) {
                int xx = w - 1 + dx;
                xv[dy * 3 + dx] = (xx >= 0 && xx < Ww) ? cur[ty + dy][xx] : 0.f;
            }

#pragma unroll
        for (int t = 0; t < 9; ++t) {
            unsigned long long xp = pack2(xv[t]);
            const ulonglong2* wp = (const ulonglong2*)&swt[ci * 252 + t * 28];
#pragma unroll
            for (int j = 0; j < 7; ++j) {
                ulonglong2 w2 = wp[j];
                fma2(acc2[2 * j],     xp, w2.x);
                fma2(acc2[2 * j + 1], xp, w2.y);
            }
        }

        if (ci + 1 < CPG && ldr)
            *(float4*)&sx[(ci + 1) & 1][lrow][lseg * 4] = nv;
        __syncthreads();
    }

    size_t outb = ((size_t)b * OCOFF) * HW + h * 64 + w;
#pragma unroll
    for (int j = 0; j < 14; ++j) {
        float lo = __uint_as_float((uint32_t)acc2[j]);
        float hi = __uint_as_float((uint32_t)(acc2[j] >> 32));
        int oc0 = 2 * j, oc1 = 2 * j + 1;
        g_part[cg][outb + (size_t)oc0 * HW] = lo;
        if (oc1 < OCOFF) g_part[cg][outb + (size_t)oc1 * HW] = hi;
    }
}

// ===========================================================================
// Kernel B: fused offset-reduce + deform-sample -> fp16 cols [k][n].
// Gathers from fp16 x in [c][hw] layout (lane-coalesced).
// ===========================================================================
__global__ __launch_bounds__(288)
void build_cols_kernel(const float* __restrict__ b_off) {
    int tid = threadIdx.x;
    int n_l = tid & 31;
    int kk  = tid >> 5;                // 0..8
    int n0  = blockIdx.x * 32;
    int n   = n0 + n_l;
    int b   = n >> 12;
    int hw  = n & 4095;
    int h   = hw >> 6, w = hw & 63;

    size_t pbase = ((size_t)b * OCOFF) * HW + hw;
    float oy = b_off[kk], ox = b_off[9 + kk], ms = b_off[18 + kk];
#pragma unroll
    for (int g = 0; g < CSPLIT; ++g) {
        oy += g_part[g][pbase + (size_t)kk * HW];
        ox += g_part[g][pbase + (size_t)(9 + kk) * HW];
        ms += g_part[g][pbase + (size_t)(18 + kk) * HW];
    }
    float m = 1.f / (1.f + expf(-ms));

    float py = (float)(h - 1 + kk / 3) + oy;
    float px = (float)(w - 1 + kk % 3) + ox;
    float y0f = floorf(py), x0f = floorf(px);
    float wy = py - y0f, wx = px - x0f;
    int y0 = (int)y0f, x0 = (int)x0f;

    bool yv0 = (y0 >= 0) & (y0 < Hh);
    bool yv1 = (y0 + 1 >= 0) & (y0 + 1 < Hh);
    bool xv0 = (x0 >= 0) & (x0 < Ww);
    bool xv1 = (x0 + 1 >= 0) & (x0 + 1 < Ww);

    float w00 = m * (1.f - wy) * (1.f - wx) * (float)(yv0 & xv0);
    float w01 = m * (1.f - wy) * wx         * (float)(yv0 & xv1);
    float w10 = m * wy * (1.f - wx)         * (float)(yv1 & xv0);
    float w11 = m * wy * wx                 * (float)(yv1 & xv1);

    int y0c = min(max(y0, 0), Hh - 1);
    int y1c = min(max(y0 + 1, 0), Hh - 1);
    int x0c = min(max(x0, 0), Ww - 1);
    int x1c = min(max(x0 + 1, 0), Ww - 1);
    int o00 = y0c * 64 + x0c, o01 = y0c * 64 + x1c;
    int o10 = y1c * 64 + x0c, o11 = y1c * 64 + x1c;

    const __half* xb = g_x16 + (size_t)b * Cc * HW;

#pragma unroll 1
    for (int c0 = 0; c0 < Cc; c0 += 8) {
        float val[8];
#pragma unroll
        for (int cl = 0; cl < 8; ++cl) {
            const __half* xc = xb + (size_t)(c0 + cl) * HW;
            val[cl] = __half2float(xc[o00]) * w00 + __half2float(xc[o01]) * w01
                    + __half2float(xc[o10]) * w10 + __half2float(xc[o11]) * w11;
        }
#pragma unroll
        for (int cl = 0; cl < 8; ++cl) {
            size_t off = (size_t)((c0 + cl) * 9 + kk) * NTOT + n;
            g_cols[off] = __half_as_ushort(__float2half_rn(val[cl]));
        }
    }
}

// ===========================================================================
// Kernel C: single-chain fp16 HMMA GEMM.  M=256 x N=128, K=2304.
// 512 threads, 16 warps (4M x 4N), 4-stage cp.async, register-fragment
// double buffering across ks steps.
// ===========================================================================
#define B_OFF  32768
#define STAGEB 49152
#define GSM    196608
#define NCHUNK 36

__device__ __forceinline__ void load_chunk(uint32_t sbu, uint32_t stoff, int chunk,
                                           int bn, int tid) {
    int kw = chunk * 64;
    uint32_t base = sbu + stoff;
    int r = tid >> 3, q = tid & 7;
#pragma unroll
    for (int rr = 0; rr < 4; ++rr) {
        int row = r + rr * 64;
        uint32_t o = swz((uint32_t)(row * 128 + q * 16));
        cp16(base + o, &g_A[(size_t)row * KTOT + kw + q * 8]);
    }
    {
        const uint16_t* s = &g_cols[(size_t)(kw + r) * NTOT + bn];
        cp16(base + B_OFF + swz2((uint32_t)(r * 256 + q * 16)),       s + q * 8);
        cp16(base + B_OFF + swz2((uint32_t)(r * 256 + (q + 8) * 16)), s + (q + 8) * 8);
    }
}

__global__ __launch_bounds__(512, 1)
void gemm_mma_kernel(const float* __restrict__ bias,
                     const float* __restrict__ gamma,
                     const float* __restrict__ beta,
                     const float* __restrict__ rmean,
                     const float* __restrict__ rvar,
                     float* __restrict__ out) {
    extern __shared__ char smc[];
    uint32_t sbu = smem_u32(smc);
    int tid  = threadIdx.x;
    int lane = tid & 31;
    int wid  = tid >> 5;
    int bn = blockIdx.x * 128;
    int warp_m = wid & 3;
    int warp_n = wid >> 2;

    int mi   = lane >> 3;
    int mrow = lane & 7;
    int rbit = ((mi & 1) << 3) + mrow;
    int cbit = (mi >> 1) << 4;
    int klane = ((mi >> 1) << 3) + mrow;
    int nlane = (mi & 1) << 3;

    int arow0 = warp_m * 64;
    int brow0 = warp_n * 32;

    // per-ks LDSM addresses (swizzled), as functions of ks
    float acc[4][4][4];
#pragma unroll
    for (int a = 0; a < 4; ++a)
#pragma unroll
        for (int b2 = 0; b2 < 4; ++b2)
#pragma unroll
            for (int c2 = 0; c2 < 4; ++c2) acc[a][b2][c2] = 0.f;

    load_chunk(sbu, 0 * STAGEB, 0, bn, tid); CP_COMMIT();
    load_chunk(sbu, 1 * STAGEB, 1, bn, tid); CP_COMMIT();
    load_chunk(sbu, 2 * STAGEB, 2, bn, tid); CP_COMMIT();

    for (int i = 0; i < NCHUNK; ++i) {
        int st = i & 3;
        CP_WAIT2();
        __syncthreads();

        if (i + 3 < NCHUNK)
            load_chunk(sbu, ((i + 3) & 3) * STAGEB, i + 3, bn, tid);
        CP_COMMIT();

        uint32_t base = sbu + st * STAGEB;

        uint32_t bq[2][2][4], af[2][4][4];
        // preload ks=0 fragments
#pragma unroll
        for (int ng = 0; ng < 2; ++ng)
            ldsm4t(bq[0][ng], base + B_OFF +
                   swz2((uint32_t)(klane * 256 + (brow0 + ng * 16 + nlane) * 2)));
#pragma unroll
        for (int mt = 0; mt < 4; ++mt)
            ldsm4(af[0][mt], base +
                  swz((uint32_t)((arow0 + mt * 16 + rbit) * 128 + cbit)));

#pragma unroll
        for (int ks = 0; ks < 4; ++ks) {
            int cur = ks & 1, nxt = cur ^ 1;
            if (ks < 3) {
                // prefetch ks+1 fragments while MMAs of ks issue below
#pragma unroll
                for (int ng = 0; ng < 2; ++ng)
                    ldsm4t(bq[nxt][ng], base + B_OFF +
                           swz2((uint32_t)(((ks + 1) * 16 + klane) * 256
                                + (brow0 + ng * 16 + nlane) * 2)));
#pragma unroll
                for (int mt = 0; mt < 4; ++mt)
                    ldsm4(af[nxt][mt], base +
                          swz((uint32_t)((arow0 + mt * 16 + rbit) * 128
                               + (ks + 1) * 32 + cbit)));
            }
#pragma unroll
            for (int mt = 0; mt < 4; ++mt)
#pragma unroll
                for (int ng = 0; ng < 2; ++ng) {
                    mma16816(acc[mt][ng * 2 + 0], af[cur][mt],
                             bq[cur][ng][0], bq[cur][ng][2]);
                    mma16816(acc[mt][ng * 2 + 1], af[cur][mt],
                             bq[cur][ng][1], bq[cur][ng][3]);
                }
        }
        __syncthreads();
    }

    int nbase = bn + warp_n * 32;
#pragma unroll
    for (int mt = 0; mt < 4; ++mt) {
        int o0 = warp_m * 64 + mt * 16 + (lane >> 2);
        int o1 = o0 + 8;
        float inv0 = gamma[o0] * rsqrtf(rvar[o0] + 1e-5f);
        float sh0  = beta[o0] - rmean[o0] * inv0 + bias[o0] * inv0;
        float inv1 = gamma[o1] * rsqrtf(rvar[o1] + 1e-5f);
        float sh1  = beta[o1] - rmean[o1] * inv1 + bias[o1] * inv1;
#pragma unroll
        for (int nt = 0; nt < 4; ++nt) {
            int n = nbase + nt * 8 + ((lane & 3) << 1);
            int bimg = n >> 12;
            int hw   = n & 4095;
            float2 v0, v1;
            v0.x = fmaxf(fmaf(acc[mt][nt][0], inv0, sh0), 0.f);
            v0.y = fmaxf(fmaf(acc[mt][nt][1], inv0, sh0), 0.f);
            v1.x = fmaxf(fmaf(acc[mt][nt][2], inv1, sh1), 0.f);
            v1.y = fmaxf(fmaf(acc[mt][nt][3], inv1, sh1), 0.f);
            *(float2*)&out[(((size_t)(bimg * Oo + o0)) << 12) + hw] = v0;
            *(float2*)&out[(((size_t)(bimg * Oo + o1)) << 12) + hw] = v1;
        }
    }
}

// ===========================================================================
extern "C" void kernel_launch(void* const* d_in, const int* in_sizes, int n_in,
                              void* d_out, int out_size) {
    const float* x      = (const float*)d_in[0];
    const float* w_off  = (const float*)d_in[1];
    const float* b_off  = (const float*)d_in[2];
    const float* weight = (const float*)d_in[3];
    const float* bias   = (const float*)d_in[4];
    const float* gamma  = (const float*)d_in[5];
    const float* beta   = (const float*)d_in[6];
    const float* rmean  = (const float*)d_in[7];
    const float* rvar   = (const float*)d_in[8];
    float* out = (float*)d_out;

    cudaFuncSetAttribute(gemm_mma_kernel,
                         cudaFuncAttributeMaxDynamicSharedMemorySize, GSM);

    prep_kernel<<<XB + WB, 256>>>(x, weight);
    offset_conv_part<<<Bb * 16 * CSPLIT, 256>>>(x, w_off);
    build_cols_kernel<<<NTOT / 32, 288>>>(b_off);

    gemm_mma_kernel<<<NTOT / 128, 512, GSM>>>(bias, gamma, beta, rmean, rvar, out);
}

// round 14
// speedup vs baseline: 1.1696x; 1.0839x over previous
#include <cuda_runtime.h>
#include <cuda_fp16.h>
#include <math.h>
#include <stdint.h>

#define Bb   8
#define Cc   256
#define Hh   64
#define Ww   64
#define Oo   256
#define HW   4096
#define OCOFF 27
#define KTOT 2304            /* K = C*9 */
#define NTOT 32768           /* B*H*W */

// ---------------- scratch (__device__ globals) ------------------------------
__device__ float    g_om[Bb * OCOFF * HW];             // offsets + sigmoid(mask)
__device__ uint16_t g_cols[(size_t)KTOT * NTOT];       // fp16 cols, [k][n]
__device__ uint16_t g_A[Oo * KTOT];                    // weight fp16, [o][k]
__device__ uint16_t g_WoffH[32 * KTOT];                // w_off fp16 hi (27 pad 32)
__device__ uint16_t g_WoffL[32 * KTOT];                // w_off fp16 residual
__device__ __half   g_x16[(size_t)Bb * Cc * HW];       // fp16 copy of x

// ---------------- helpers ----------------------------------------------------
__device__ __forceinline__ uint32_t smem_u32(const void* p) {
    uint32_t a;
    asm("{ .reg .u64 t; cvta.to.shared.u64 t, %1; cvt.u32.u64 %0, t; }" : "=r"(a) : "l"(p));
    return a;
}
__device__ __forceinline__ uint32_t swz(uint32_t off)  { return off ^ ((off >> 3) & 0x70); }
__device__ __forceinline__ uint32_t swz2(uint32_t off) { return off ^ ((off >> 4) & 0x70); }

__device__ __forceinline__ void cp16(uint32_t dst, const void* src) {
    asm volatile("cp.async.cg.shared.global [%0], [%1], 16;" :: "r"(dst), "l"(src));
}
#define CP_COMMIT() asm volatile("cp.async.commit_group;" ::: "memory")
#define CP_WAIT1()  asm volatile("cp.async.wait_group 1;" ::: "memory")
#define CP_WAIT2()  asm volatile("cp.async.wait_group 2;" ::: "memory")

__device__ __forceinline__ void ldsm4(uint32_t* r, uint32_t addr) {
    asm volatile("ldmatrix.sync.aligned.m8n8.x4.shared.b16 {%0,%1,%2,%3}, [%4];"
                 : "=r"(r[0]), "=r"(r[1]), "=r"(r[2]), "=r"(r[3]) : "r"(addr));
}
__device__ __forceinline__ void ldsm4t(uint32_t* r, uint32_t addr) {
    asm volatile("ldmatrix.sync.aligned.m8n8.x4.trans.shared.b16 {%0,%1,%2,%3}, [%4];"
                 : "=r"(r[0]), "=r"(r[1]), "=r"(r[2]), "=r"(r[3]) : "r"(addr));
}
__device__ __forceinline__ void mma16816(float* c, const uint32_t* a,
                                         uint32_t b0, uint32_t b1) {
    asm volatile("mma.sync.aligned.m16n8k16.row.col.f32.f16.f16.f32 "
                 "{%0,%1,%2,%3}, {%4,%5,%6,%7}, {%8,%9}, {%0,%1,%2,%3};"
                 : "+f"(c[0]), "+f"(c[1]), "+f"(c[2]), "+f"(c[3])
                 : "r"(a[0]), "r"(a[1]), "r"(a[2]), "r"(a[3]), "r"(b0), "r"(b1));
}

// ===========================================================================
// Kernel P: fused prep — x->fp16 (blocks [0,XB)), weight->fp16 ([XB,XB+WB)),
// w_off -> fp16 hi/lo padded to 32 rows ([XB+WB, XB+WB+WOB))
// ===========================================================================
#define XB  8192
#define WB  2304
#define WOB 288     /* 32*2304/256 */
__global__ void prep_kernel(const float* __restrict__ x,
                            const float* __restrict__ weight,
                            const float* __restrict__ w_off) {
    int blk = blockIdx.x;
    if (blk < XB) {
        size_t i = ((size_t)blk * 256 + threadIdx.x) * 4;
        float4 v = *(const float4*)&x[i];
        __half2 lo = __floats2half2_rn(v.x, v.y);
        __half2 hi = __floats2half2_rn(v.z, v.w);
        *(uint32_t*)&g_x16[i]     = *(uint32_t*)&lo;
        *(uint32_t*)&g_x16[i + 2] = *(uint32_t*)&hi;
    } else if (blk < XB + WB) {
        int idx = (blk - XB) * 256 + threadIdx.x;
        g_A[idx] = __half_as_ushort(__float2half_rn(weight[idx]));
    } else {
        int idx = (blk - XB - WB) * 256 + threadIdx.x;   // over 32*2304
        int row = idx / KTOT;
        float wv = (row < OCOFF) ? w_off[idx] : 0.f;
        __half h = __float2half_rn(wv);
        __half l = __float2half_rn(wv - __half2float(h));
        g_WoffH[idx] = __half_as_ushort(h);
        g_WoffL[idx] = __half_as_ushort(l);
    }
}

// ===========================================================================
// Kernel A: offset conv via HMMA (2-chain hi/lo).  M=32(27) x N=128, K=2304.
// B = im2col of x16 built in smem per chunk (fixed shifts, coalesced loads).
// 256 threads, 8 warps (2M x 4N). Epilogue: +b_off, sigmoid(mask) -> g_om.
// ===========================================================================
#define OG_A0   0            /* A stage s: s*8192 (H at +0, L at +4096) */
#define OG_B    16384        /* B tile: 64 k-rows x 256B = 16KB */
#define OG_SMEM 32768
#define OG_NCH  36

__global__ __launch_bounds__(256)
void offconv_gemm_kernel(const float* __restrict__ b_off) {
    extern __shared__ char smc[];
    uint32_t sbu = smem_u32(smc);
    int tid  = threadIdx.x;
    int lane = tid & 31;
    int wid  = tid >> 5;
    int n0   = blockIdx.x * 128;
    int b    = n0 >> 12;
    int hw0  = n0 & 4095;
    int h0   = hw0 >> 6;

    int warp_m = wid & 1;                 // 2 warps along M (16 each)
    int warp_n = wid >> 1;                // 4 warps along N (32 each)

    int mi   = lane >> 3;
    int mrow = lane & 7;
    int rbit = ((mi & 1) << 3) + mrow;
    int cbit = (mi >> 1) << 4;
    int klane = ((mi >> 1) << 3) + mrow;
    int nlane = (mi & 1) << 3;

    // B-builder coords: 1 k-row x 32 channels... (n fixed per thread)
    int n_l   = tid & 127;
    int khalf = tid >> 7;                 // 0..1 (32 k-rows each)
    int bh = h0 + (n_l >> 6);
    int bw = n_l & 63;
    const __half* xb = g_x16 + (size_t)b * Cc * HW;

    // A cp.async coords
    int arow = tid >> 3, aq = tid & 7;

    float acc[4][4];
#pragma unroll
    for (int a = 0; a < 4; ++a)
#pragma unroll
        for (int c2 = 0; c2 < 4; ++c2) acc[a][c2] = 0.f;

    // prologue: A chunk 0
    {
        uint32_t o = swz((uint32_t)(arow * 128 + aq * 16));
        cp16(sbu + o,        &g_WoffH[(size_t)arow * KTOT + aq * 8]);
        cp16(sbu + 4096 + o, &g_WoffL[(size_t)arow * KTOT + aq * 8]);
    }
    CP_COMMIT();

    for (int i = 0; i < OG_NCH; ++i) {
        // build B tile for chunk i (32 elements per thread, coalesced LDGs)
        {
            int k0 = i * 64 + khalf * 32;
            int c  = k0 / 9;
            int kk = k0 - c * 9;
            const __half* xc = xb + (size_t)c * HW;
#pragma unroll
            for (int j = 0; j < 32; ++j) {
                int ky = (kk * 11) >> 5;          // kk/3 for kk in [0,8]
                int kx = kk - ky * 3;
                int y  = bh - 1 + ky;
                int xx = bw - 1 + kx;
                bool v = (y >= 0) & (y < Hh) & (xx >= 0) & (xx < Ww);
                __half val = v ? xc[y * 64 + xx] : __float2half_rn(0.f);
                uint32_t so = swz2((uint32_t)((khalf * 32 + j) * 256 + n_l * 2));
                *(__half*)(smc + OG_B + so) = val;
                if (++kk == 9) { kk = 0; ++c; xc += HW; }
            }
        }
        // A chunk i+1
        if (i + 1 < OG_NCH) {
            uint32_t st = ((i + 1) & 1) * 8192;
            uint32_t o  = swz((uint32_t)(arow * 128 + aq * 16));
            cp16(sbu + st + o,        &g_WoffH[(size_t)arow * KTOT + (i + 1) * 64 + aq * 8]);
            cp16(sbu + st + 4096 + o, &g_WoffL[(size_t)arow * KTOT + (i + 1) * 64 + aq * 8]);
        }
        CP_COMMIT();
        CP_WAIT1();
        __syncthreads();

        uint32_t abase = sbu + (i & 1) * 8192;
        int arow0 = warp_m * 16;
        int brow0 = warp_n * 32;
#pragma unroll
        for (int ks = 0; ks < 4; ++ks) {
            uint32_t bq[2][4], ah[4], al[4];
#pragma unroll
            for (int ng = 0; ng < 2; ++ng)
                ldsm4t(bq[ng], sbu + OG_B +
                       swz2((uint32_t)((ks * 16 + klane) * 256
                            + (brow0 + ng * 16 + nlane) * 2)));
            uint32_t ao = swz((uint32_t)((arow0 + rbit) * 128 + ks * 32 + cbit));
            ldsm4(ah, abase + ao);
            ldsm4(al, abase + 4096 + ao);
#pragma unroll
            for (int ng = 0; ng < 2; ++ng) {
                mma16816(acc[ng * 2 + 0], ah, bq[ng][0], bq[ng][2]);
                mma16816(acc[ng * 2 + 1], ah, bq[ng][1], bq[ng][3]);
                mma16816(acc[ng * 2 + 0], al, bq[ng][0], bq[ng][2]);
                mma16816(acc[ng * 2 + 1], al, bq[ng][1], bq[ng][3]);
            }
        }
        __syncthreads();
    }

    // epilogue: +b_off, sigmoid on mask channels, write g_om (oc < 27)
    int r0 = warp_m * 16 + (lane >> 2);
    int r1 = r0 + 8;
#pragma unroll
    for (int a = 0; a < 4; ++a) {
        int col = warp_n * 32 + (a >> 1) * 16 + (a & 1) * 8 + ((lane & 3) << 1);
#pragma unroll
        for (int c2 = 0; c2 < 4; ++c2) {
            int o  = (c2 < 2) ? r0 : r1;
            int cc = col + (c2 & 1);
            if (o < OCOFF) {
                float v = acc[a][c2] + b_off[o];
                if (o >= 18) v = 1.f / (1.f + expf(-v));
                g_om[((size_t)b * OCOFF + o) * HW + hw0 + cc] = v;
            }
        }
    }
}

// ===========================================================================
// Kernel B: deform-sample -> fp16 cols [k][n] (reads g_om directly).
// ===========================================================================
__global__ __launch_bounds__(288)
void build_cols_kernel() {
    int tid = threadIdx.x;
    int n_l = tid & 31;
    int kk  = tid >> 5;                // 0..8
    int n0  = blockIdx.x * 32;
    int n   = n0 + n_l;
    int b   = n >> 12;
    int hw  = n & 4095;
    int h   = hw >> 6, w = hw & 63;

    size_t obase = ((size_t)b * OCOFF) * HW + hw;
    float oy = g_om[obase + (size_t)kk * HW];
    float ox = g_om[obase + (size_t)(9 + kk) * HW];
    float m  = g_om[obase + (size_t)(18 + kk) * HW];

    float py = (float)(h - 1 + kk / 3) + oy;
    float px = (float)(w - 1 + kk % 3) + ox;
    float y0f = floorf(py), x0f = floorf(px);
    float wy = py - y0f, wx = px - x0f;
    int y0 = (int)y0f, x0 = (int)x0f;

    bool yv0 = (y0 >= 0) & (y0 < Hh);
    bool yv1 = (y0 + 1 >= 0) & (y0 + 1 < Hh);
    bool xv0 = (x0 >= 0) & (x0 < Ww);
    bool xv1 = (x0 + 1 >= 0) & (x0 + 1 < Ww);

    float w00 = m * (1.f - wy) * (1.f - wx) * (float)(yv0 & xv0);
    float w01 = m * (1.f - wy) * wx         * (float)(yv0 & xv1);
    float w10 = m * wy * (1.f - wx)         * (float)(yv1 & xv0);
    float w11 = m * wy * wx                 * (float)(yv1 & xv1);

    int y0c = min(max(y0, 0), Hh - 1);
    int y1c = min(max(y0 + 1, 0), Hh - 1);
    int x0c = min(max(x0, 0), Ww - 1);
    int x1c = min(max(x0 + 1, 0), Ww - 1);
    int o00 = y0c * 64 + x0c, o01 = y0c * 64 + x1c;
    int o10 = y1c * 64 + x0c, o11 = y1c * 64 + x1c;

    const __half* xb = g_x16 + (size_t)b * Cc * HW;

#pragma unroll 1
    for (int c0 = 0; c0 < Cc; c0 += 8) {
        float val[8];
#pragma unroll
        for (int cl = 0; cl < 8; ++cl) {
            const __half* xc = xb + (size_t)(c0 + cl) * HW;
            val[cl] = __half2float(xc[o00]) * w00 + __half2float(xc[o01]) * w01
                    + __half2float(xc[o10]) * w10 + __half2float(xc[o11]) * w11;
        }
#pragma unroll
        for (int cl = 0; cl < 8; ++cl) {
            size_t off = (size_t)((c0 + cl) * 9 + kk) * NTOT + n;
            g_cols[off] = __half_as_ushort(__float2half_rn(val[cl]));
        }
    }
}

// ===========================================================================
// Kernel C: single-chain fp16 HMMA GEMM.  M=256 x N=128, K=2304.
// 512 threads, 16 warps (4M x 4N), 4-stage cp.async.
// ===========================================================================
#define B_OFF  32768
#define STAGEB 49152
#define GSM    196608
#define NCHUNK 36

__device__ __forceinline__ void load_chunk(uint32_t sbu, uint32_t stoff, int chunk,
                                           int bn, int tid) {
    int kw = chunk * 64;
    uint32_t base = sbu + stoff;
    int r = tid >> 3, q = tid & 7;
#pragma unroll
    for (int rr = 0; rr < 4; ++rr) {
        int row = r + rr * 64;
        uint32_t o = swz((uint32_t)(row * 128 + q * 16));
        cp16(base + o, &g_A[(size_t)row * KTOT + kw + q * 8]);
    }
    {
        const uint16_t* s = &g_cols[(size_t)(kw + r) * NTOT + bn];
        cp16(base + B_OFF + swz2((uint32_t)(r * 256 + q * 16)),       s + q * 8);
        cp16(base + B_OFF + swz2((uint32_t)(r * 256 + (q + 8) * 16)), s + (q + 8) * 8);
    }
}

__global__ __launch_bounds__(512, 1)
void gemm_mma_kernel(const float* __restrict__ bias,
                     const float* __restrict__ gamma,
                     const float* __restrict__ beta,
                     const float* __restrict__ rmean,
                     const float* __restrict__ rvar,
                     float* __restrict__ out) {
    extern __shared__ char smc[];
    uint32_t sbu = smem_u32(smc);
    int tid  = threadIdx.x;
    int lane = tid & 31;
    int wid  = tid >> 5;
    int bn = blockIdx.x * 128;
    int warp_m = wid & 3;
    int warp_n = wid >> 2;

    int mi   = lane >> 3;
    int mrow = lane & 7;
    int rbit = ((mi & 1) << 3) + mrow;
    int cbit = (mi >> 1) << 4;
    int klane = ((mi >> 1) << 3) + mrow;
    int nlane = (mi & 1) << 3;

    float acc[4][4][4];
#pragma unroll
    for (int a = 0; a < 4; ++a)
#pragma unroll
        for (int b2 = 0; b2 < 4; ++b2)
#pragma unroll
            for (int c2 = 0; c2 < 4; ++c2) acc[a][b2][c2] = 0.f;

    load_chunk(sbu, 0 * STAGEB, 0, bn, tid); CP_COMMIT();
    load_chunk(sbu, 1 * STAGEB, 1, bn, tid); CP_COMMIT();
    load_chunk(sbu, 2 * STAGEB, 2, bn, tid); CP_COMMIT();

    int arow0 = warp_m * 64;
    int brow0 = warp_n * 32;

    for (int i = 0; i < NCHUNK; ++i) {
        int st = i & 3;
        CP_WAIT2();
        __syncthreads();

        if (i + 3 < NCHUNK)
            load_chunk(sbu, ((i + 3) & 3) * STAGEB, i + 3, bn, tid);
        CP_COMMIT();

        uint32_t base = sbu + st * STAGEB;
#pragma unroll
        for (int ks = 0; ks < 4; ++ks) {
            uint32_t bq[2][4], af[4][4];
#pragma unroll
            for (int ng = 0; ng < 2; ++ng)
                ldsm4t(bq[ng], base + B_OFF +
                       swz2((uint32_t)((ks * 16 + klane) * 256
                            + (brow0 + ng * 16 + nlane) * 2)));
#pragma unroll
            for (int mt = 0; mt < 4; ++mt)
                ldsm4(af[mt], base +
                      swz((uint32_t)((arow0 + mt * 16 + rbit) * 128 + ks * 32 + cbit)));

#pragma unroll
            for (int mt = 0; mt < 4; ++mt)
#pragma unroll
                for (int ng = 0; ng < 2; ++ng) {
                    mma16816(acc[mt][ng * 2 + 0], af[mt], bq[ng][0], bq[ng][2]);
                    mma16816(acc[mt][ng * 2 + 1], af[mt], bq[ng][1], bq[ng][3]);
                }
        }
        __syncthreads();
    }

    int nbase = bn + warp_n * 32;
#pragma unroll
    for (int mt = 0; mt < 4; ++mt) {
        int o0 = warp_m * 64 + mt * 16 + (lane >> 2);
        int o1 = o0 + 8;
        float inv0 = gamma[o0] * rsqrtf(rvar[o0] + 1e-5f);
        float sh0  = beta[o0] - rmean[o0] * inv0 + bias[o0] * inv0;
        float inv1 = gamma[o1] * rsqrtf(rvar[o1] + 1e-5f);
        float sh1  = beta[o1] - rmean[o1] * inv1 + bias[o1] * inv1;
#pragma unroll
        for (int nt = 0; nt < 4; ++nt) {
            int n = nbase + nt * 8 + ((lane & 3) << 1);
            int bimg = n >> 12;
            int hw   = n & 4095;
            float2 v0, v1;
            v0.x = fmaxf(fmaf(acc[mt][nt][0], inv0, sh0), 0.f);
            v0.y = fmaxf(fmaf(acc[mt][nt][1], inv0, sh0), 0.f);
            v1.x = fmaxf(fmaf(acc[mt][nt][2], inv1, sh1), 0.f);
            v1.y = fmaxf(fmaf(acc[mt][nt][3], inv1, sh1), 0.f);
            *(float2*)&out[(((size_t)(bimg * Oo + o0)) << 12) + hw] = v0;
            *(float2*)&out[(((size_t)(bimg * Oo + o1)) << 12) + hw] = v1;
        }
    }
}

// ===========================================================================
extern "C" void kernel_launch(void* const* d_in, const int* in_sizes, int n_in,
                              void* d_out, int out_size) {
    const float* x      = (const float*)d_in[0];
    const float* w_off  = (const float*)d_in[1];
    const float* b_off  = (const float*)d_in[2];
    const float* weight = (const float*)d_in[3];
    const float* bias   = (const float*)d_in[4];
    const float* gamma  = (const float*)d_in[5];
    const float* beta   = (const float*)d_in[6];
    const float* rmean  = (const float*)d_in[7];
    const float* rvar   = (const float*)d_in[8];
    float* out = (float*)d_out;

    cudaFuncSetAttribute(gemm_mma_kernel,
                         cudaFuncAttributeMaxDynamicSharedMemorySize, GSM);
    cudaFuncSetAttribute(offconv_gemm_kernel,
                         cudaFuncAttributeMaxDynamicSharedMemorySize, OG_SMEM);

    prep_kernel<<<XB + WB + WOB, 256>>>(x, weight, w_off);
    offconv_gemm_kernel<<<NTOT / 128, 256, OG_SMEM>>>(b_off);
    build_cols_kernel<<<NTOT / 32, 288>>>();

    gemm_mma_kernel<<<NTOT / 128, 512, GSM>>>(bias, gamma, beta, rmean, rvar, out);
}

// round 15
// speedup vs baseline: 1.3013x; 1.1126x over previous
#include <cuda_runtime.h>
#include <cuda_fp16.h>
#include <math.h>
#include <stdint.h>

#define Bb   8
#define Cc   256
#define Hh   64
#define Ww   64
#define Oo   256
#define HW   4096
#define OCOFF 27
#define KTOT 2304            /* K = C*9 */
#define NTOT 32768           /* B*H*W */
#define XTOT ((size_t)Bb * Cc * HW)

// ---------------- scratch (__device__ globals) ------------------------------
__device__ float    g_om[Bb * OCOFF * HW];             // offsets + sigmoid(mask)
__device__ uint16_t g_cols[(size_t)KTOT * NTOT];       // fp16 cols, [k][n]
__device__ uint16_t g_A[Oo * KTOT];                    // weight fp16, [o][k]
__device__ uint16_t g_WoffH[32 * KTOT];                // w_off fp16 hi (27 pad 32)
__device__ uint16_t g_WoffL[32 * KTOT];                // w_off fp16 residual
__device__ __half   g_xA[XTOT];                        // fp16 x
__device__ __half   g_xB[XTOT];                        // fp16 x shifted by 1 elem

// ---------------- helpers ----------------------------------------------------
__device__ __forceinline__ uint32_t smem_u32(const void* p) {
    uint32_t a;
    asm("{ .reg .u64 t; cvta.to.shared.u64 t, %1; cvt.u32.u64 %0, t; }" : "=r"(a) : "l"(p));
    return a;
}
__device__ __forceinline__ uint32_t swz(uint32_t off)  { return off ^ ((off >> 3) & 0x70); }
__device__ __forceinline__ uint32_t swz2(uint32_t off) { return off ^ ((off >> 4) & 0x70); }

__device__ __forceinline__ void cp16(uint32_t dst, const void* src) {
    asm volatile("cp.async.cg.shared.global [%0], [%1], 16;" :: "r"(dst), "l"(src));
}
#define CP_COMMIT() asm volatile("cp.async.commit_group;" ::: "memory")
#define CP_WAIT1()  asm volatile("cp.async.wait_group 1;" ::: "memory")
#define CP_WAIT2()  asm volatile("cp.async.wait_group 2;" ::: "memory")

__device__ __forceinline__ void ldsm4(uint32_t* r, uint32_t addr) {
    asm volatile("ldmatrix.sync.aligned.m8n8.x4.shared.b16 {%0,%1,%2,%3}, [%4];"
                 : "=r"(r[0]), "=r"(r[1]), "=r"(r[2]), "=r"(r[3]) : "r"(addr));
}
__device__ __forceinline__ void ldsm4t(uint32_t* r, uint32_t addr) {
    asm volatile("ldmatrix.sync.aligned.m8n8.x4.trans.shared.b16 {%0,%1,%2,%3}, [%4];"
                 : "=r"(r[0]), "=r"(r[1]), "=r"(r[2]), "=r"(r[3]) : "r"(addr));
}
__device__ __forceinline__ void mma16816(float* c, const uint32_t* a,
                                         uint32_t b0, uint32_t b1) {
    asm volatile("mma.sync.aligned.m16n8k16.row.col.f32.f16.f16.f32 "
                 "{%0,%1,%2,%3}, {%4,%5,%6,%7}, {%8,%9}, {%0,%1,%2,%3};"
                 : "+f"(c[0]), "+f"(c[1]), "+f"(c[2]), "+f"(c[3])
                 : "r"(a[0]), "r"(a[1]), "r"(a[2]), "r"(a[3]), "r"(b0), "r"(b1));
}

// ===========================================================================
// Kernel P: fused prep — x->fp16 (XB), x-shifted->fp16 (XB2),
// weight->fp16 (WB), w_off hi/lo (WOB)
// ===========================================================================
#define XB  8192
#define XB2 8192
#define WB  2304
#define WOB 288
__global__ void prep_kernel(const float* __restrict__ x,
                            const float* __restrict__ weight,
                            const float* __restrict__ w_off) {
    int blk = blockIdx.x;
    if (blk < XB) {
        size_t i = ((size_t)blk * 256 + threadIdx.x) * 4;
        float4 v = *(const float4*)&x[i];
        __half2 lo = __floats2half2_rn(v.x, v.y);
        __half2 hi = __floats2half2_rn(v.z, v.w);
        *(uint32_t*)&g_xA[i]     = *(uint32_t*)&lo;
        *(uint32_t*)&g_xA[i + 2] = *(uint32_t*)&hi;
    } else if (blk < XB + XB2) {
        size_t i = ((size_t)(blk - XB) * 256 + threadIdx.x) * 4;
        float a0 = x[i + 1];
        float a1 = x[i + 2];
        float a2 = x[i + 3];
        float a3 = (i + 4 < XTOT) ? x[i + 4] : 0.f;
        __half2 lo = __floats2half2_rn(a0, a1);
        __half2 hi = __floats2half2_rn(a2, a3);
        *(uint32_t*)&g_xB[i]     = *(uint32_t*)&lo;
        *(uint32_t*)&g_xB[i + 2] = *(uint32_t*)&hi;
    } else if (blk < XB + XB2 + WB) {
        int idx = (blk - XB - XB2) * 256 + threadIdx.x;
        g_A[idx] = __half_as_ushort(__float2half_rn(weight[idx]));
    } else {
        int idx = (blk - XB - XB2 - WB) * 256 + threadIdx.x;
        int row = idx / KTOT;
        float wv = (row < OCOFF) ? w_off[idx] : 0.f;
        __half h = __float2half_rn(wv);
        __half l = __float2half_rn(wv - __half2float(h));
        g_WoffH[idx] = __half_as_ushort(h);
        g_WoffL[idx] = __half_as_ushort(l);
    }
}

// ===========================================================================
// Kernel A: offset conv via HMMA (2-chain hi/lo).  M=32(27) x N=128, K=2304.
// ===========================================================================
#define OG_B    16384
#define OG_SMEM 32768
#define OG_NCH  36

__global__ __launch_bounds__(256)
void offconv_gemm_kernel(const float* __restrict__ b_off) {
    extern __shared__ char smc[];
    uint32_t sbu = smem_u32(smc);
    int tid  = threadIdx.x;
    int lane = tid & 31;
    int wid  = tid >> 5;
    int n0   = blockIdx.x * 128;
    int b    = n0 >> 12;
    int hw0  = n0 & 4095;
    int h0   = hw0 >> 6;

    int warp_m = wid & 1;
    int warp_n = wid >> 1;

    int mi   = lane >> 3;
    int mrow = lane & 7;
    int rbit = ((mi & 1) << 3) + mrow;
    int cbit = (mi >> 1) << 4;
    int klane = ((mi >> 1) << 3) + mrow;
    int nlane = (mi & 1) << 3;

    int n_l   = tid & 127;
    int khalf = tid >> 7;
    int bh = h0 + (n_l >> 6);
    int bw = n_l & 63;
    const __half* xb = g_xA + (size_t)b * Cc * HW;

    int arow = tid >> 3, aq = tid & 7;

    float acc[4][4];
#pragma unroll
    for (int a = 0; a < 4; ++a)
#pragma unroll
        for (int c2 = 0; c2 < 4; ++c2) acc[a][c2] = 0.f;

    {
        uint32_t o = swz((uint32_t)(arow * 128 + aq * 16));
        cp16(sbu + o,        &g_WoffH[(size_t)arow * KTOT + aq * 8]);
        cp16(sbu + 4096 + o, &g_WoffL[(size_t)arow * KTOT + aq * 8]);
    }
    CP_COMMIT();

    for (int i = 0; i < OG_NCH; ++i) {
        {
            int k0 = i * 64 + khalf * 32;
            int c  = k0 / 9;
            int kk = k0 - c * 9;
            const __half* xc = xb + (size_t)c * HW;
#pragma unroll
            for (int j = 0; j < 32; ++j) {
                int ky = (kk * 11) >> 5;
                int kx = kk - ky * 3;
                int y  = bh - 1 + ky;
                int xx = bw - 1 + kx;
                bool v = (y >= 0) & (y < Hh) & (xx >= 0) & (xx < Ww);
                __half val = v ? xc[y * 64 + xx] : __float2half_rn(0.f);
                uint32_t so = swz2((uint32_t)((khalf * 32 + j) * 256 + n_l * 2));
                *(__half*)(smc + OG_B + so) = val;
                if (++kk == 9) { kk = 0; ++c; xc += HW; }
            }
        }
        if (i + 1 < OG_NCH) {
            uint32_t st = ((i + 1) & 1) * 8192;
            uint32_t o  = swz((uint32_t)(arow * 128 + aq * 16));
            cp16(sbu + st + o,        &g_WoffH[(size_t)arow * KTOT + (i + 1) * 64 + aq * 8]);
            cp16(sbu + st + 4096 + o, &g_WoffL[(size_t)arow * KTOT + (i + 1) * 64 + aq * 8]);
        }
        CP_COMMIT();
        CP_WAIT1();
        __syncthreads();

        uint32_t abase = sbu + (i & 1) * 8192;
        int arow0 = warp_m * 16;
        int brow0 = warp_n * 32;
#pragma unroll
        for (int ks = 0; ks < 4; ++ks) {
            uint32_t bq[2][4], ah[4], al[4];
#pragma unroll
            for (int ng = 0; ng < 2; ++ng)
                ldsm4t(bq[ng], sbu + OG_B +
                       swz2((uint32_t)((ks * 16 + klane) * 256
                            + (brow0 + ng * 16 + nlane) * 2)));
            uint32_t ao = swz((uint32_t)((arow0 + rbit) * 128 + ks * 32 + cbit));
            ldsm4(ah, abase + ao);
            ldsm4(al, abase + 4096 + ao);
#pragma unroll
            for (int ng = 0; ng < 2; ++ng) {
                mma16816(acc[ng * 2 + 0], ah, bq[ng][0], bq[ng][2]);
                mma16816(acc[ng * 2 + 1], ah, bq[ng][1], bq[ng][3]);
                mma16816(acc[ng * 2 + 0], al, bq[ng][0], bq[ng][2]);
                mma16816(acc[ng * 2 + 1], al, bq[ng][1], bq[ng][3]);
            }
        }
        __syncthreads();
    }

    int r0 = warp_m * 16 + (lane >> 2);
    int r1 = r0 + 8;
#pragma unroll
    for (int a = 0; a < 4; ++a) {
        int col = warp_n * 32 + (a >> 1) * 16 + (a & 1) * 8 + ((lane & 3) << 1);
#pragma unroll
        for (int c2 = 0; c2 < 4; ++c2) {
            int o  = (c2 < 2) ? r0 : r1;
            int cc = col + (c2 & 1);
            if (o < OCOFF) {
                float v = acc[a][c2] + b_off[o];
                if (o >= 18) v = 1.f / (1.f + expf(-v));
                g_om[((size_t)b * OCOFF + o) * HW + hw0 + cc] = v;
            }
        }
    }
}

// ===========================================================================
// Kernel B: deform-sample -> fp16 cols [k][n].
// Aligned __half2 pixel-pair gathers (dual-copy trick): 2 LDG.32 per channel.
// ===========================================================================
__global__ __launch_bounds__(288)
void build_cols_kernel() {
    int tid = threadIdx.x;
    int n_l = tid & 31;
    int kk  = tid >> 5;                // 0..8
    int n0  = blockIdx.x * 32;
    int n   = n0 + n_l;
    int b   = n >> 12;
    int hw  = n & 4095;
    int h   = hw >> 6, w = hw & 63;

    size_t obase = ((size_t)b * OCOFF) * HW + hw;
    float oy = g_om[obase + (size_t)kk * HW];
    float ox = g_om[obase + (size_t)(9 + kk) * HW];
    float m  = g_om[obase + (size_t)(18 + kk) * HW];

    float py = (float)(h - 1 + kk / 3) + oy;
    float px = (float)(w - 1 + kk % 3) + ox;
    float y0f = floorf(py), x0f = floorf(px);
    float wy = py - y0f, wx = px - x0f;
    int y0 = (int)y0f, x0 = (int)x0f;

    bool yv0 = (y0 >= 0) & (y0 < Hh);
    bool yv1 = (y0 + 1 >= 0) & (y0 + 1 < Hh);
    bool xv0 = (x0 >= 0) & (x0 < Ww);
    bool xv1 = (x0 + 1 >= 0) & (x0 + 1 < Ww);

    float w00 = m * (1.f - wy) * (1.f - wx) * (float)(yv0 & xv0);
    float w01 = m * (1.f - wy) * wx         * (float)(yv0 & xv1);
    float w10 = m * wy * (1.f - wx)         * (float)(yv1 & xv0);
    float w11 = m * wy * wx                 * (float)(yv1 & xv1);

    int y0c = min(max(y0, 0), Hh - 1);
    int y1c = min(max(y0 + 1, 0), Hh - 1);
    int x0c = min(max(x0, 0), Ww - 1);
    int x1c = min(max(x0 + 1, 0), Ww - 1);

    // aligned pair base: x0c, x1c ∈ {base, base+1}
    int base = min(max(x0, 0), Ww - 2);
    int odd  = base & 1;
    int e    = base - odd;               // even, <= 60 when odd, <= 62 when even

    // permuted weights (computed once)
    float lo0 = w00 * (x0c == base)     + w01 * (x1c == base);
    float hi0 = w00 * (x0c == base + 1) + w01 * (x1c == base + 1);
    float lo1 = w10 * (x0c == base)     + w11 * (x1c == base);
    float hi1 = w10 * (x0c == base + 1) + w11 * (x1c == base + 1);

    const __half* xsel = (odd ? g_xB : g_xA) + (size_t)b * Cc * HW + e;
    const uint32_t* p0 = (const uint32_t*)(xsel + y0c * 64);
    const uint32_t* p1 = (const uint32_t*)(xsel + y1c * 64);

#pragma unroll 1
    for (int c0 = 0; c0 < Cc; c0 += 8) {
        float val[8];
#pragma unroll
        for (int cl = 0; cl < 8; ++cl) {
            int ci = (c0 + cl) * (HW / 2);
            float2 a = __half22float2(*(const __half2*)&p0[ci]);
            float2 d = __half22float2(*(const __half2*)&p1[ci]);
            val[cl] = a.x * lo0 + a.y * hi0 + d.x * lo1 + d.y * hi1;
        }
#pragma unroll
        for (int cl = 0; cl < 8; ++cl) {
            size_t off = (size_t)((c0 + cl) * 9 + kk) * NTOT + n;
            g_cols[off] = __half_as_ushort(__float2half_rn(val[cl]));
        }
    }
}

// ===========================================================================
// Kernel C: single-chain fp16 HMMA GEMM.  M=256 x N=128, K=2304.
// 512 threads, 16 warps (4M x 4N), 4-stage cp.async. One barrier per chunk.
// ===========================================================================
#define B_OFF  32768
#define STAGEB 49152
#define GSM    196608
#define NCHUNK 36

__device__ __forceinline__ void load_chunk(uint32_t sbu, uint32_t stoff, int chunk,
                                           int bn, int tid) {
    int kw = chunk * 64;
    uint32_t base = sbu + stoff;
    int r = tid >> 3, q = tid & 7;
#pragma unroll
    for (int rr = 0; rr < 4; ++rr) {
        int row = r + rr * 64;
        uint32_t o = swz((uint32_t)(row * 128 + q * 16));
        cp16(base + o, &g_A[(size_t)row * KTOT + kw + q * 8]);
    }
    {
        const uint16_t* s = &g_cols[(size_t)(kw + r) * NTOT + bn];
        cp16(base + B_OFF + swz2((uint32_t)(r * 256 + q * 16)),       s + q * 8);
        cp16(base + B_OFF + swz2((uint32_t)(r * 256 + (q + 8) * 16)), s + (q + 8) * 8);
    }
}

__global__ __launch_bounds__(512, 1)
void gemm_mma_kernel(const float* __restrict__ bias,
                     const float* __restrict__ gamma,
                     const float* __restrict__ beta,
                     const float* __restrict__ rmean,
                     const float* __restrict__ rvar,
                     float* __restrict__ out) {
    extern __shared__ char smc[];
    uint32_t sbu = smem_u32(smc);
    int tid  = threadIdx.x;
    int lane = tid & 31;
    int wid  = tid >> 5;
    int bn = blockIdx.x * 128;
    int warp_m = wid & 3;
    int warp_n = wid >> 2;

    int mi   = lane >> 3;
    int mrow = lane & 7;
    int rbit = ((mi & 1) << 3) + mrow;
    int cbit = (mi >> 1) << 4;
    int klane = ((mi >> 1) << 3) + mrow;
    int nlane = (mi & 1) << 3;

    float acc[4][4][4];
#pragma unroll
    for (int a = 0; a < 4; ++a)
#pragma unroll
        for (int b2 = 0; b2 < 4; ++b2)
#pragma unroll
            for (int c2 = 0; c2 < 4; ++c2) acc[a][b2][c2] = 0.f;

    load_chunk(sbu, 0 * STAGEB, 0, bn, tid); CP_COMMIT();
    load_chunk(sbu, 1 * STAGEB, 1, bn, tid); CP_COMMIT();
    load_chunk(sbu, 2 * STAGEB, 2, bn, tid); CP_COMMIT();

    int arow0 = warp_m * 64;
    int brow0 = warp_n * 32;

    for (int i = 0; i < NCHUNK; ++i) {
        int st = i & 3;
        CP_WAIT2();
        __syncthreads();

        if (i + 3 < NCHUNK)
            load_chunk(sbu, ((i + 3) & 3) * STAGEB, i + 3, bn, tid);
        CP_COMMIT();

        uint32_t base = sbu + st * STAGEB;
#pragma unroll
        for (int ks = 0; ks < 4; ++ks) {
            uint32_t bq[2][4], af[4][4];
#pragma unroll
            for (int ng = 0; ng < 2; ++ng)
                ldsm4t(bq[ng], base + B_OFF +
                       swz2((uint32_t)((ks * 16 + klane) * 256
                            + (brow0 + ng * 16 + nlane) * 2)));
#pragma unroll
            for (int mt = 0; mt < 4; ++mt)
                ldsm4(af[mt], base +
                      swz((uint32_t)((arow0 + mt * 16 + rbit) * 128 + ks * 32 + cbit)));

#pragma unroll
            for (int mt = 0; mt < 4; ++mt)
#pragma unroll
                for (int ng = 0; ng < 2; ++ng) {
                    mma16816(acc[mt][ng * 2 + 0], af[mt], bq[ng][0], bq[ng][2]);
                    mma16816(acc[mt][ng * 2 + 1], af[mt], bq[ng][1], bq[ng][3]);
                }
        }
        // NOTE: no second barrier — next iteration's top barrier orders the
        // stage reuse (cp.async writes are issued only after it).
    }

    int nbase = bn + warp_n * 32;
#pragma unroll
    for (int mt = 0; mt < 4; ++mt) {
        int o0 = warp_m * 64 + mt * 16 + (lane >> 2);
        int o1 = o0 + 8;
        float inv0 = gamma[o0] * rsqrtf(rvar[o0] + 1e-5f);
        float sh0  = beta[o0] - rmean[o0] * inv0 + bias[o0] * inv0;
        float inv1 = gamma[o1] * rsqrtf(rvar[o1] + 1e-5f);
        float sh1  = beta[o1] - rmean[o1] * inv1 + bias[o1] * inv1;
#pragma unroll
        for (int nt = 0; nt < 4; ++nt) {
            int n = nbase + nt * 8 + ((lane & 3) << 1);
            int bimg = n >> 12;
            int hw   = n & 4095;
            float2 v0, v1;
            v0.x = fmaxf(fmaf(acc[mt][nt][0], inv0, sh0), 0.f);
            v0.y = fmaxf(fmaf(acc[mt][nt][1], inv0, sh0), 0.f);
            v1.x = fmaxf(fmaf(acc[mt][nt][2], inv1, sh1), 0.f);
            v1.y = fmaxf(fmaf(acc[mt][nt][3], inv1, sh1), 0.f);
            *(float2*)&out[(((size_t)(bimg * Oo + o0)) << 12) + hw] = v0;
            *(float2*)&out[(((size_t)(bimg * Oo + o1)) << 12) + hw] = v1;
        }
    }
}

// ===========================================================================
extern "C" void kernel_launch(void* const* d_in, const int* in_sizes, int n_in,
                              void* d_out, int out_size) {
    const float* x      = (const float*)d_in[0];
    const float* w_off  = (const float*)d_in[1];
    const float* b_off  = (const float*)d_in[2];
    const float* weight = (const float*)d_in[3];
    const float* bias   = (const float*)d_in[4];
    const float* gamma  = (const float*)d_in[5];
    const float* beta   = (const float*)d_in[6];
    const float* rmean  = (const float*)d_in[7];
    const float* rvar   = (const float*)d_in[8];
    float* out = (float*)d_out;

    cudaFuncSetAttribute(gemm_mma_kernel,
                         cudaFuncAttributeMaxDynamicSharedMemorySize, GSM);
    cudaFuncSetAttribute(offconv_gemm_kernel,
                         cudaFuncAttributeMaxDynamicSharedMemorySize, OG_SMEM);

    prep_kernel<<<XB + XB2 + WB + WOB, 256>>>(x, weight, w_off);
    offconv_gemm_kernel<<<NTOT / 128, 256, OG_SMEM>>>(b_off);
    build_cols_kernel<<<NTOT / 32, 288>>>();

    gemm_mma_kernel<<<NTOT / 128, 512, GSM>>>(bias, gamma, beta, rmean, rvar, out);
}